// round 10
// baseline (speedup 1.0000x reference)
#include <cuda_runtime.h>
#include <cuda_fp16.h>
#include <cstdint>

#define M_TOK 8192
#define K_DIM 4096
#define N_OUT 4096
#define NGRP  16
#define KB2   (K_DIM * 2)               // row stride in bytes (fp16)

// ---- scratch (device globals; no allocation allowed) ----
__device__ __align__(16) __half g_a16[(size_t)M_TOK * K_DIM];   // fp16(q - zp), exact ints
__device__ __align__(16) __half g_b16[(size_t)N_OUT * K_DIM];   // fp16((w - z) * s)
__device__ float g_sx[M_TOK];                                    // per-token scale

// ============================================================================
// Fused prep kernel: blocks [0,8192) per-token quant -> g_a16,
//                    blocks [8192,12288) weight dequant -> g_b16
// ============================================================================
__global__ __launch_bounds__(256) void prep_kernel(const float* __restrict__ x,
                                                   const int* __restrict__ W,
                                                   const float* __restrict__ scales,
                                                   const float* __restrict__ zeros) {
    int tid = threadIdx.x;
    if (blockIdx.x < M_TOK) {
        int row = blockIdx.x;
        const float4* xr4 = reinterpret_cast<const float4*>(x + (size_t)row * K_DIM) + tid * 4;

        float4 v[4];
#pragma unroll
        for (int i = 0; i < 4; i++) v[i] = xr4[i];

        float mn = 0.0f, mx = 0.0f;
#pragma unroll
        for (int i = 0; i < 4; i++) {
            mn = fminf(mn, fminf(fminf(v[i].x, v[i].y), fminf(v[i].z, v[i].w)));
            mx = fmaxf(mx, fmaxf(fmaxf(v[i].x, v[i].y), fmaxf(v[i].z, v[i].w)));
        }
#pragma unroll
        for (int off = 16; off; off >>= 1) {
            mn = fminf(mn, __shfl_xor_sync(0xffffffffu, mn, off));
            mx = fmaxf(mx, __shfl_xor_sync(0xffffffffu, mx, off));
        }
        __shared__ float smn[8], smx[8];
        if ((tid & 31) == 0) { smn[tid >> 5] = mn; smx[tid >> 5] = mx; }
        __syncthreads();
        mn = smn[0]; mx = smx[0];
#pragma unroll
        for (int i = 1; i < 8; i++) { mn = fminf(mn, smn[i]); mx = fmaxf(mx, smx[i]); }

        float scale = fmaxf((mx - mn) / 255.0f, 1.1920928955078125e-07f);
        float a = mn / scale, b = mx / scale;
        float t = (-128.0f + a) + (127.0f + b);
        float zp0 = (t > 0.0f) ? (-128.0f - a) : (127.0f - b);
        float zpf = fminf(fmaxf(rintf(zp0), -128.0f), 127.0f);

        const float* pv = reinterpret_cast<const float*>(v);
        uint32_t packed[8];
#pragma unroll
        for (int j = 0; j < 8; j++) {
            float q0 = fminf(fmaxf(rintf(pv[2 * j] / scale) + zpf, -128.0f), 127.0f);
            float q1 = fminf(fmaxf(rintf(pv[2 * j + 1] / scale) + zpf, -128.0f), 127.0f);
            __half2 h = __floats2half2_rn(q0 - zpf, q1 - zpf);   // exact ints in [-255,255]
            packed[j] = *reinterpret_cast<uint32_t*>(&h);
        }
        uint4* dst = reinterpret_cast<uint4*>(g_a16 + (size_t)row * K_DIM + tid * 16);
        dst[0] = make_uint4(packed[0], packed[1], packed[2], packed[3]);
        dst[1] = make_uint4(packed[4], packed[5], packed[6], packed[7]);
        if (tid == 0) g_sx[row] = scale;
    } else {
        int o = blockIdx.x - M_TOK;
        int g = tid >> 4;
        float z = zeros[o * NGRP + g];
        float s = scales[o * NGRP + g];

        const int4* Wrow = reinterpret_cast<const int4*>(W + (size_t)o * K_DIM) + tid * 4;
        uint32_t packed[8];
#pragma unroll
        for (int c = 0; c < 4; c++) {
            int4 w4 = Wrow[c];
            __half2 h0 = __floats2half2_rn(((float)w4.x - z) * s, ((float)w4.y - z) * s);
            __half2 h1 = __floats2half2_rn(((float)w4.z - z) * s, ((float)w4.w - z) * s);
            packed[2 * c]     = *reinterpret_cast<uint32_t*>(&h0);
            packed[2 * c + 1] = *reinterpret_cast<uint32_t*>(&h1);
        }
        uint4* dst = reinterpret_cast<uint4*>(g_b16 + (size_t)o * K_DIM + tid * 16);
        dst[0] = make_uint4(packed[0], packed[1], packed[2], packed[3]);
        dst[1] = make_uint4(packed[4], packed[5], packed[6], packed[7]);
    }
}

// ============================================================================
// GEMM: 128x128 block, 64x32 warp tiles, 3-stage cp.async, 2 CTAs/SM
// ============================================================================
#define BM 128
#define BN 128
#define NSTAGE 3
#define A_TILE (BM * 128)                 // 16384 bytes
#define B_TILE (BN * 128)                 // 16384 bytes
#define STAGE_B (A_TILE + B_TILE)         // 32768
#define SMEM_DYN (NSTAGE * STAGE_B + 1024)
#define KITERS (K_DIM / 64)               // 64
#define ROWSTEP (32 * KB2)                // gmem delta per cp.async slice

__device__ __forceinline__ uint32_t s2u(const void* p) {
    uint32_t a;
    asm("{ .reg .u64 t; cvta.to.shared.u64 t, %1; cvt.u32.u64 %0, t; }" : "=r"(a) : "l"(p));
    return a;
}
__device__ __forceinline__ uint32_t swz(uint32_t r, uint32_t c16) {
    uint32_t off = r * 128 + c16 * 16;
    return off ^ ((off >> 3) & 0x70);
}
__device__ __forceinline__ void ldsm4(uint32_t& d0, uint32_t& d1, uint32_t& d2, uint32_t& d3,
                                      uint32_t addr) {
    asm volatile("ldmatrix.sync.aligned.m8n8.x4.shared.b16 {%0,%1,%2,%3}, [%4];"
                 : "=r"(d0), "=r"(d1), "=r"(d2), "=r"(d3) : "r"(addr));
}
__device__ __forceinline__ void mma_f16(float& c0, float& c1, float& c2, float& c3,
                                        uint32_t a0, uint32_t a1, uint32_t a2, uint32_t a3,
                                        uint32_t b0, uint32_t b1) {
    asm volatile(
        "mma.sync.aligned.m16n8k16.row.col.f32.f16.f16.f32 "
        "{%0,%1,%2,%3}, {%4,%5,%6,%7}, {%8,%9}, {%0,%1,%2,%3};\n"
        : "+f"(c0), "+f"(c1), "+f"(c2), "+f"(c3)
        : "r"(a0), "r"(a1), "r"(a2), "r"(a3), "r"(b0), "r"(b1));
}

__global__ __launch_bounds__(256, 2) void gemm_kernel(float* __restrict__ out) {
    extern __shared__ char smem_raw[];
    char* sm = (char*)(((uintptr_t)smem_raw + 1023) & ~(uintptr_t)1023);
    uint32_t sbase = s2u(sm);

    int tid = threadIdx.x, lane = tid & 31, wid = tid >> 5;
    int warpm = wid & 1, warpn = wid >> 1;        // 2 x 4 warp grid, warp tile 64x32
    int gid = lane >> 2, tig = lane & 3;
    int bn = blockIdx.x, bm = blockIdx.y;

    // base ldmatrix offsets (ks=0); ks variant = base ^ (ks<<5)
    uint32_t aoffb[4], boffb[2];
    {
        int g8 = lane >> 3, rin = lane & 7;
#pragma unroll
        for (int mt = 0; mt < 4; mt++)
            aoffb[mt] = swz(warpm * 64 + mt * 16 + (g8 & 1) * 8 + rin, g8 >> 1);
#pragma unroll
        for (int p = 0; p < 2; p++)
            boffb[p] = A_TILE + swz(warpn * 32 + p * 16 + (g8 >> 1) * 8 + rin, g8 & 1);
    }

    const char* Ag = (const char*)g_a16 + (size_t)bm * BM * KB2;
    const char* Bg = (const char*)g_b16 + (size_t)bn * BN * KB2;

    // cp.async bases; slice i adds i*4096 (smem) / i*ROWSTEP (gmem); 4 slices each
    uint32_t sa0 = swz(tid >> 3, tid & 7);
    uint32_t g0  = (uint32_t)((tid >> 3) * KB2 + (tid & 7) * 16);

#define ISSUE(kc)                                                                              \
    {                                                                                          \
        uint32_t st = sbase + ((kc) % NSTAGE) * STAGE_B + sa0;                                 \
        uint32_t kb = g0 + (kc) * 128;                                                         \
        _Pragma("unroll") for (int i = 0; i < 4; i++)                                          \
            asm volatile("cp.async.cg.shared.global [%0], [%1], 16;"                           \
                         :: "r"(st + i * 4096), "l"(Ag + kb + i * ROWSTEP) : "memory");        \
        _Pragma("unroll") for (int i = 0; i < 4; i++)                                          \
            asm volatile("cp.async.cg.shared.global [%0], [%1], 16;"                           \
                         :: "r"(st + A_TILE + i * 4096), "l"(Bg + kb + i * ROWSTEP) : "memory"); \
        asm volatile("cp.async.commit_group;" ::: "memory");                                   \
    }

    float c[4][4][4];
#pragma unroll
    for (int mt = 0; mt < 4; mt++)
#pragma unroll
        for (int nt = 0; nt < 4; nt++)
#pragma unroll
            for (int r = 0; r < 4; r++) c[mt][nt][r] = 0.0f;

    // prologue: fill 2 stages
    ISSUE(0); ISSUE(1);

    for (int kc = 0; kc < KITERS; ++kc) {
        asm volatile("cp.async.wait_group 1;" ::: "memory");
        __syncthreads();
        if (kc + NSTAGE - 1 < KITERS) ISSUE(kc + NSTAGE - 1);

        uint32_t sA = sbase + (kc % NSTAGE) * STAGE_B;
#pragma unroll
        for (int ks = 0; ks < 4; ks++) {
            uint32_t a[4][4], b[2][4];
#pragma unroll
            for (int mt = 0; mt < 4; mt++)
                ldsm4(a[mt][0], a[mt][1], a[mt][2], a[mt][3], sA + (aoffb[mt] ^ (ks << 5)));
#pragma unroll
            for (int p = 0; p < 2; p++)
                ldsm4(b[p][0], b[p][1], b[p][2], b[p][3], sA + (boffb[p] ^ (ks << 5)));
#pragma unroll
            for (int mt = 0; mt < 4; mt++)
#pragma unroll
                for (int nt = 0; nt < 4; nt++)
                    mma_f16(c[mt][nt][0], c[mt][nt][1], c[mt][nt][2], c[mt][nt][3],
                            a[mt][0], a[mt][1], a[mt][2], a[mt][3],
                            b[nt >> 1][(nt & 1) * 2], b[nt >> 1][(nt & 1) * 2 + 1]);
        }
        __syncthreads();
    }

    // epilogue: out[m,o] = sx[m] * acc  (B already carries weight scales)
#pragma unroll
    for (int mt = 0; mt < 4; ++mt) {
        int rlo = bm * BM + warpm * 64 + mt * 16 + gid;
        int rhi = rlo + 8;
        float sxl = g_sx[rlo];
        float sxh = g_sx[rhi];
#pragma unroll
        for (int nt = 0; nt < 4; ++nt) {
            int o0 = bn * BN + warpn * 32 + nt * 8 + tig * 2;
            float2 vlo = make_float2(sxl * c[mt][nt][0], sxl * c[mt][nt][1]);
            float2 vhi = make_float2(sxh * c[mt][nt][2], sxh * c[mt][nt][3]);
            *reinterpret_cast<float2*>(out + (size_t)rlo * N_OUT + o0) = vlo;
            *reinterpret_cast<float2*>(out + (size_t)rhi * N_OUT + o0) = vhi;
        }
    }
}

// ============================================================================
// launch
// ============================================================================
extern "C" void kernel_launch(void* const* d_in, const int* in_sizes, int n_in,
                              void* d_out, int out_size) {
    const float* x      = (const float*)d_in[0];
    const int*   w      = (const int*)d_in[1];     // int8 upcast to int32 by harness
    const float* scales = (const float*)d_in[2];
    const float* zeros  = (const float*)d_in[3];
    float* out = (float*)d_out;

    cudaFuncSetAttribute(gemm_kernel, cudaFuncAttributeMaxDynamicSharedMemorySize, SMEM_DYN);

    prep_kernel<<<M_TOK + N_OUT, 256>>>(x, w, scales, zeros);
    gemm_kernel<<<dim3(N_OUT / BN, M_TOK / BM), 256, SMEM_DYN>>>(out);
}

// round 11
// speedup vs baseline: 1.0079x; 1.0079x over previous
#include <cuda_runtime.h>
#include <cuda_fp16.h>
#include <cstdint>

#define M_TOK 8192
#define K_DIM 4096
#define N_OUT 4096
#define NGRP  16
#define KB2   (K_DIM * 2)               // row stride in bytes (fp16)

// ---- scratch (device globals; no allocation allowed) ----
__device__ __align__(16) __half g_a16[(size_t)M_TOK * K_DIM];   // fp16(q - zp), exact ints
__device__ __align__(16) __half g_b16[(size_t)N_OUT * K_DIM];   // fp16((w - z) * s)
__device__ float g_sx[M_TOK];                                    // per-token scale

// ============================================================================
// Fused prep kernel: blocks [0,8192) per-token quant -> g_a16,
//                    blocks [8192,12288) weight dequant -> g_b16
// ============================================================================
__global__ __launch_bounds__(256) void prep_kernel(const float* __restrict__ x,
                                                   const int* __restrict__ W,
                                                   const float* __restrict__ scales,
                                                   const float* __restrict__ zeros) {
    int tid = threadIdx.x;
    if (blockIdx.x < M_TOK) {
        int row = blockIdx.x;
        const float4* xr4 = reinterpret_cast<const float4*>(x + (size_t)row * K_DIM) + tid * 4;

        float4 v[4];
#pragma unroll
        for (int i = 0; i < 4; i++) v[i] = xr4[i];

        float mn = 0.0f, mx = 0.0f;
#pragma unroll
        for (int i = 0; i < 4; i++) {
            mn = fminf(mn, fminf(fminf(v[i].x, v[i].y), fminf(v[i].z, v[i].w)));
            mx = fmaxf(mx, fmaxf(fmaxf(v[i].x, v[i].y), fmaxf(v[i].z, v[i].w)));
        }
#pragma unroll
        for (int off = 16; off; off >>= 1) {
            mn = fminf(mn, __shfl_xor_sync(0xffffffffu, mn, off));
            mx = fmaxf(mx, __shfl_xor_sync(0xffffffffu, mx, off));
        }
        __shared__ float smn[8], smx[8];
        if ((tid & 31) == 0) { smn[tid >> 5] = mn; smx[tid >> 5] = mx; }
        __syncthreads();
        mn = smn[0]; mx = smx[0];
#pragma unroll
        for (int i = 1; i < 8; i++) { mn = fminf(mn, smn[i]); mx = fmaxf(mx, smx[i]); }

        float scale = fmaxf((mx - mn) / 255.0f, 1.1920928955078125e-07f);
        float a = mn / scale, b = mx / scale;
        float t = (-128.0f + a) + (127.0f + b);
        float zp0 = (t > 0.0f) ? (-128.0f - a) : (127.0f - b);
        float zpf = fminf(fmaxf(rintf(zp0), -128.0f), 127.0f);

        const float* pv = reinterpret_cast<const float*>(v);
        uint32_t packed[8];
#pragma unroll
        for (int j = 0; j < 8; j++) {
            float q0 = fminf(fmaxf(rintf(pv[2 * j] / scale) + zpf, -128.0f), 127.0f);
            float q1 = fminf(fmaxf(rintf(pv[2 * j + 1] / scale) + zpf, -128.0f), 127.0f);
            __half2 h = __floats2half2_rn(q0 - zpf, q1 - zpf);   // exact ints in [-255,255]
            packed[j] = *reinterpret_cast<uint32_t*>(&h);
        }
        uint4* dst = reinterpret_cast<uint4*>(g_a16 + (size_t)row * K_DIM + tid * 16);
        dst[0] = make_uint4(packed[0], packed[1], packed[2], packed[3]);
        dst[1] = make_uint4(packed[4], packed[5], packed[6], packed[7]);
        if (tid == 0) g_sx[row] = scale;
    } else {
        int o = blockIdx.x - M_TOK;
        int g = tid >> 4;
        float z = zeros[o * NGRP + g];
        float s = scales[o * NGRP + g];

        const int4* Wrow = reinterpret_cast<const int4*>(W + (size_t)o * K_DIM) + tid * 4;
        uint32_t packed[8];
#pragma unroll
        for (int c = 0; c < 4; c++) {
            int4 w4 = Wrow[c];
            __half2 h0 = __floats2half2_rn(((float)w4.x - z) * s, ((float)w4.y - z) * s);
            __half2 h1 = __floats2half2_rn(((float)w4.z - z) * s, ((float)w4.w - z) * s);
            packed[2 * c]     = *reinterpret_cast<uint32_t*>(&h0);
            packed[2 * c + 1] = *reinterpret_cast<uint32_t*>(&h1);
        }
        uint4* dst = reinterpret_cast<uint4*>(g_b16 + (size_t)o * K_DIM + tid * 16);
        dst[0] = make_uint4(packed[0], packed[1], packed[2], packed[3]);
        dst[1] = make_uint4(packed[4], packed[5], packed[6], packed[7]);
    }
}

// ============================================================================
// GEMM: 128x256 block, 64x64 warp tiles, BK=128 double-subtile stages,
//       2-stage cp.async (192 KB), boundary every 8 ks in MMA shadow
// ============================================================================
#define BM 128
#define BN 256
#define A_SUB (BM * 128)                  // 16384 bytes (one 64-K A subtile)
#define B_SUB (BN * 128)                  // 32768 bytes (one 64-K B subtile)
#define A_TILE (2 * A_SUB)                // 32768
#define B_TILE (2 * B_SUB)                // 65536
#define STAGE_B (A_TILE + B_TILE)         // 98304
#define NSTAGE 2
#define SMEM_DYN (NSTAGE * STAGE_B + 1024)
#define K2ITERS (K_DIM / 128)             // 32
#define ROWSTEP (32 * KB2)                // gmem delta per cp.async slice
#define B_BASE A_TILE                     // B region offset within stage

__device__ __forceinline__ uint32_t s2u(const void* p) {
    uint32_t a;
    asm("{ .reg .u64 t; cvta.to.shared.u64 t, %1; cvt.u32.u64 %0, t; }" : "=r"(a) : "l"(p));
    return a;
}
__device__ __forceinline__ uint32_t swz(uint32_t r, uint32_t c16) {
    uint32_t off = r * 128 + c16 * 16;
    return off ^ ((off >> 3) & 0x70);
}
__device__ __forceinline__ void ldsm4(uint32_t& d0, uint32_t& d1, uint32_t& d2, uint32_t& d3,
                                      uint32_t addr) {
    asm volatile("ldmatrix.sync.aligned.m8n8.x4.shared.b16 {%0,%1,%2,%3}, [%4];"
                 : "=r"(d0), "=r"(d1), "=r"(d2), "=r"(d3) : "r"(addr));
}
__device__ __forceinline__ void mma_f16(float& c0, float& c1, float& c2, float& c3,
                                        uint32_t a0, uint32_t a1, uint32_t a2, uint32_t a3,
                                        uint32_t b0, uint32_t b1) {
    asm volatile(
        "mma.sync.aligned.m16n8k16.row.col.f32.f16.f16.f32 "
        "{%0,%1,%2,%3}, {%4,%5,%6,%7}, {%8,%9}, {%0,%1,%2,%3};\n"
        : "+f"(c0), "+f"(c1), "+f"(c2), "+f"(c3)
        : "r"(a0), "r"(a1), "r"(a2), "r"(a3), "r"(b0), "r"(b1));
}

__global__ __launch_bounds__(256, 1) void gemm_kernel(float* __restrict__ out) {
    extern __shared__ char smem_raw[];
    char* sm = (char*)(((uintptr_t)smem_raw + 1023) & ~(uintptr_t)1023);
    uint32_t sbase = s2u(sm);

    int tid = threadIdx.x, lane = tid & 31, wid = tid >> 5;
    int warpm = wid & 1, warpn = wid >> 1;        // 2 x 4 warp grid, warp tile 64x64
    int gid = lane >> 2, tig = lane & 3;
    int bn = blockIdx.x, bm = blockIdx.y;

    // base ldmatrix offsets within a subtile (ks2=0); ks2 variant = base ^ (ks2<<5)
    uint32_t aoffb[4], boffb[4];
    {
        int g8 = lane >> 3, rin = lane & 7;
#pragma unroll
        for (int mt = 0; mt < 4; mt++)
            aoffb[mt] = swz(warpm * 64 + mt * 16 + (g8 & 1) * 8 + rin, g8 >> 1);
#pragma unroll
        for (int p = 0; p < 4; p++)
            boffb[p] = B_BASE + swz(warpn * 64 + p * 16 + (g8 >> 1) * 8 + rin, g8 & 1);
    }

    const char* Ag = (const char*)g_a16 + (size_t)bm * BM * KB2;
    const char* Bg = (const char*)g_b16 + (size_t)bn * BN * KB2;

    // cp.async bases
    uint32_t sa0 = swz(tid >> 3, tid & 7);
    uint32_t g0  = (uint32_t)((tid >> 3) * KB2 + (tid & 7) * 16);

    // stage layout: [A0 16K][A1 16K][B0 32K][B1 32K]; gmem k-byte = kc2*256 + half*128
#define ISSUE2(kc2)                                                                              \
    {                                                                                            \
        uint32_t st = sbase + ((kc2) & 1) * STAGE_B + sa0;                                       \
        uint32_t kb = g0 + (kc2) * 256;                                                          \
        _Pragma("unroll") for (int h = 0; h < 2; h++)                                            \
            _Pragma("unroll") for (int i = 0; i < 4; i++)                                        \
                asm volatile("cp.async.cg.shared.global [%0], [%1], 16;"                         \
                             :: "r"(st + h * A_SUB + i * 4096),                                  \
                                "l"(Ag + kb + h * 128 + i * ROWSTEP) : "memory");                \
        _Pragma("unroll") for (int h = 0; h < 2; h++)                                            \
            _Pragma("unroll") for (int i = 0; i < 8; i++)                                        \
                asm volatile("cp.async.cg.shared.global [%0], [%1], 16;"                         \
                             :: "r"(st + B_BASE + h * B_SUB + i * 4096),                         \
                                "l"(Bg + kb + h * 128 + i * ROWSTEP) : "memory");                \
        asm volatile("cp.async.commit_group;" ::: "memory");                                     \
    }

#define LOADFRAG(buf, stg, half, ks2)                                                    \
    {                                                                                    \
        _Pragma("unroll") for (int mt = 0; mt < 4; mt++)                                 \
            ldsm4(a[buf][mt][0], a[buf][mt][1], a[buf][mt][2], a[buf][mt][3],            \
                  (stg) + (half) * A_SUB + (aoffb[mt] ^ ((ks2) << 5)));                  \
        _Pragma("unroll") for (int p = 0; p < 4; p++)                                    \
            ldsm4(b[buf][p][0], b[buf][p][1], b[buf][p][2], b[buf][p][3],                \
                  (stg) + (half) * B_SUB + (boffb[p] ^ ((ks2) << 5)));                   \
    }

#define MMA_ALL(buf)                                                                         \
    {                                                                                        \
        _Pragma("unroll") for (int mt = 0; mt < 4; mt++)                                     \
            _Pragma("unroll") for (int nt = 0; nt < 8; nt++)                                 \
                mma_f16(c[mt][nt][0], c[mt][nt][1], c[mt][nt][2], c[mt][nt][3],              \
                        a[buf][mt][0], a[buf][mt][1], a[buf][mt][2], a[buf][mt][3],          \
                        b[buf][nt >> 1][(nt & 1) * 2], b[buf][nt >> 1][(nt & 1) * 2 + 1]);   \
    }

    float c[4][8][4];
#pragma unroll
    for (int mt = 0; mt < 4; mt++)
#pragma unroll
        for (int nt = 0; nt < 8; nt++)
#pragma unroll
            for (int r = 0; r < 4; r++) c[mt][nt][r] = 0.0f;

    uint32_t a[2][4][4], b[2][4][4];

    // prologue: fill both stages, wait for stage 0, load its first fragments
    ISSUE2(0); ISSUE2(1);
    asm volatile("cp.async.wait_group 1;" ::: "memory");
    __syncthreads();
    LOADFRAG(0, sbase, 0, 0);

    for (int kc2 = 0; kc2 < K2ITERS; ++kc2) {
        uint32_t stg = sbase + (kc2 & 1) * STAGE_B;
        // 8 ks-batches: halves (0,0..3) then (1,0..3); frag buffers alternate 0,1,...
        LOADFRAG(1, stg, 0, 1);  MMA_ALL(0);
        LOADFRAG(0, stg, 0, 2);  MMA_ALL(1);
        LOADFRAG(1, stg, 0, 3);  MMA_ALL(0);
        LOADFRAG(0, stg, 1, 0);  MMA_ALL(1);
        LOADFRAG(1, stg, 1, 1);  MMA_ALL(0);
        LOADFRAG(0, stg, 1, 2);  MMA_ALL(1);
        LOADFRAG(1, stg, 1, 3);  MMA_ALL(0);
        if (kc2 + 1 < K2ITERS) {
            // boundary hidden in the shadow of the last MMA batch
            asm volatile("cp.async.wait_group 0;" ::: "memory");   // next stage resident
            __syncthreads();                                        // all reads of this stage done
            if (kc2 + 2 < K2ITERS) ISSUE2(kc2 + 2);                 // refill this stage
            LOADFRAG(0, sbase + ((kc2 + 1) & 1) * STAGE_B, 0, 0);   // next kc2 first frags
            MMA_ALL(1);
        } else {
            MMA_ALL(1);
        }
    }

    // epilogue: out[m,o] = sx[m] * acc  (B already carries weight scales)
#pragma unroll
    for (int mt = 0; mt < 4; ++mt) {
        int rlo = bm * BM + warpm * 64 + mt * 16 + gid;
        int rhi = rlo + 8;
        float sxl = g_sx[rlo];
        float sxh = g_sx[rhi];
#pragma unroll
        for (int nt = 0; nt < 8; ++nt) {
            int o0 = bn * BN + warpn * 64 + nt * 8 + tig * 2;
            float2 vlo = make_float2(sxl * c[mt][nt][0], sxl * c[mt][nt][1]);
            float2 vhi = make_float2(sxh * c[mt][nt][2], sxh * c[mt][nt][3]);
            *reinterpret_cast<float2*>(out + (size_t)rlo * N_OUT + o0) = vlo;
            *reinterpret_cast<float2*>(out + (size_t)rhi * N_OUT + o0) = vhi;
        }
    }
}

// ============================================================================
// launch
// ============================================================================
extern "C" void kernel_launch(void* const* d_in, const int* in_sizes, int n_in,
                              void* d_out, int out_size) {
    const float* x      = (const float*)d_in[0];
    const int*   w      = (const int*)d_in[1];     // int8 upcast to int32 by harness
    const float* scales = (const float*)d_in[2];
    const float* zeros  = (const float*)d_in[3];
    float* out = (float*)d_out;

    cudaFuncSetAttribute(gemm_kernel, cudaFuncAttributeMaxDynamicSharedMemorySize, SMEM_DYN);

    prep_kernel<<<M_TOK + N_OUT, 256>>>(x, w, scales, zeros);
    gemm_kernel<<<dim3(N_OUT / BN, M_TOK / BM), 256, SMEM_DYN>>>(out);
}

// round 12
// speedup vs baseline: 1.0237x; 1.0157x over previous
#include <cuda_runtime.h>
#include <cuda_fp16.h>
#include <cstdint>

#define M_TOK 8192
#define K_DIM 4096
#define N_OUT 4096
#define NGRP  16
#define KB2   (K_DIM * 2)               // row stride in bytes (fp16)

// ---- scratch (device globals; no allocation allowed) ----
__device__ __align__(16) __half g_a16[(size_t)M_TOK * K_DIM];   // fp16(q - zp), exact ints
__device__ __align__(16) __half g_b16[(size_t)N_OUT * K_DIM];   // fp16((w - z) * s)
__device__ float g_sx[M_TOK];                                    // per-token scale

// ============================================================================
// Fused prep kernel: blocks [0,8192) per-token quant -> g_a16,
//                    blocks [8192,12288) weight dequant -> g_b16
// ============================================================================
__global__ __launch_bounds__(256) void prep_kernel(const float* __restrict__ x,
                                                   const int* __restrict__ W,
                                                   const float* __restrict__ scales,
                                                   const float* __restrict__ zeros) {
    int tid = threadIdx.x;
    if (blockIdx.x < M_TOK) {
        int row = blockIdx.x;
        const float4* xr4 = reinterpret_cast<const float4*>(x + (size_t)row * K_DIM) + tid * 4;

        float4 v[4];
#pragma unroll
        for (int i = 0; i < 4; i++) v[i] = xr4[i];

        float mn = 0.0f, mx = 0.0f;
#pragma unroll
        for (int i = 0; i < 4; i++) {
            mn = fminf(mn, fminf(fminf(v[i].x, v[i].y), fminf(v[i].z, v[i].w)));
            mx = fmaxf(mx, fmaxf(fmaxf(v[i].x, v[i].y), fmaxf(v[i].z, v[i].w)));
        }
#pragma unroll
        for (int off = 16; off; off >>= 1) {
            mn = fminf(mn, __shfl_xor_sync(0xffffffffu, mn, off));
            mx = fmaxf(mx, __shfl_xor_sync(0xffffffffu, mx, off));
        }
        __shared__ float smn[8], smx[8];
        if ((tid & 31) == 0) { smn[tid >> 5] = mn; smx[tid >> 5] = mx; }
        __syncthreads();
        mn = smn[0]; mx = smx[0];
#pragma unroll
        for (int i = 1; i < 8; i++) { mn = fminf(mn, smn[i]); mx = fmaxf(mx, smx[i]); }

        float scale = fmaxf((mx - mn) / 255.0f, 1.1920928955078125e-07f);
        float a = mn / scale, b = mx / scale;
        float t = (-128.0f + a) + (127.0f + b);
        float zp0 = (t > 0.0f) ? (-128.0f - a) : (127.0f - b);
        float zpf = fminf(fmaxf(rintf(zp0), -128.0f), 127.0f);

        const float* pv = reinterpret_cast<const float*>(v);
        uint32_t packed[8];
#pragma unroll
        for (int j = 0; j < 8; j++) {
            float q0 = fminf(fmaxf(rintf(pv[2 * j] / scale) + zpf, -128.0f), 127.0f);
            float q1 = fminf(fmaxf(rintf(pv[2 * j + 1] / scale) + zpf, -128.0f), 127.0f);
            __half2 h = __floats2half2_rn(q0 - zpf, q1 - zpf);   // exact ints in [-255,255]
            packed[j] = *reinterpret_cast<uint32_t*>(&h);
        }
        uint4* dst = reinterpret_cast<uint4*>(g_a16 + (size_t)row * K_DIM + tid * 16);
        dst[0] = make_uint4(packed[0], packed[1], packed[2], packed[3]);
        dst[1] = make_uint4(packed[4], packed[5], packed[6], packed[7]);
        if (tid == 0) g_sx[row] = scale;
    } else {
        int o = blockIdx.x - M_TOK;
        int g = tid >> 4;
        float z = zeros[o * NGRP + g];
        float s = scales[o * NGRP + g];

        const int4* Wrow = reinterpret_cast<const int4*>(W + (size_t)o * K_DIM) + tid * 4;
        uint32_t packed[8];
#pragma unroll
        for (int c = 0; c < 4; c++) {
            int4 w4 = Wrow[c];
            __half2 h0 = __floats2half2_rn(((float)w4.x - z) * s, ((float)w4.y - z) * s);
            __half2 h1 = __floats2half2_rn(((float)w4.z - z) * s, ((float)w4.w - z) * s);
            packed[2 * c]     = *reinterpret_cast<uint32_t*>(&h0);
            packed[2 * c + 1] = *reinterpret_cast<uint32_t*>(&h1);
        }
        uint4* dst = reinterpret_cast<uint4*>(g_b16 + (size_t)o * K_DIM + tid * 16);
        dst[0] = make_uint4(packed[0], packed[1], packed[2], packed[3]);
        dst[1] = make_uint4(packed[4], packed[5], packed[6], packed[7]);
    }
}

// ============================================================================
// GEMM: persistent CTAs, 128x256 tiles, 64x64 warp tiles, 4-stage cp.async.
// Continuous chunk stream across tiles: next tile's stages prefetched during
// the current tile's last kcs; epilogue overlaps the prefetch.
// ============================================================================
#define BM 128
#define BN 256
#define NSTAGE 4
#define A_TILE (BM * 128)                 // 16384 bytes
#define B_TILE (BN * 128)                 // 32768 bytes
#define STAGE_B (A_TILE + B_TILE)         // 49152
#define SMEM_DYN (NSTAGE * STAGE_B + 1024)
#define KITERS (K_DIM / 64)               // 64 chunks per tile
#define ROWSTEP (32 * KB2)                // gmem delta per cp.async slice
#define NTILES ((M_TOK / BM) * (N_OUT / BN))   // 1024
#define TPN (N_OUT / BN)                  // 16 tiles along n

__device__ __forceinline__ uint32_t s2u(const void* p) {
    uint32_t a;
    asm("{ .reg .u64 t; cvta.to.shared.u64 t, %1; cvt.u32.u64 %0, t; }" : "=r"(a) : "l"(p));
    return a;
}
__device__ __forceinline__ uint32_t swz(uint32_t r, uint32_t c16) {
    uint32_t off = r * 128 + c16 * 16;
    return off ^ ((off >> 3) & 0x70);
}
__device__ __forceinline__ void ldsm4(uint32_t& d0, uint32_t& d1, uint32_t& d2, uint32_t& d3,
                                      uint32_t addr) {
    asm volatile("ldmatrix.sync.aligned.m8n8.x4.shared.b16 {%0,%1,%2,%3}, [%4];"
                 : "=r"(d0), "=r"(d1), "=r"(d2), "=r"(d3) : "r"(addr));
}
__device__ __forceinline__ void mma_f16(float& c0, float& c1, float& c2, float& c3,
                                        uint32_t a0, uint32_t a1, uint32_t a2, uint32_t a3,
                                        uint32_t b0, uint32_t b1) {
    asm volatile(
        "mma.sync.aligned.m16n8k16.row.col.f32.f16.f16.f32 "
        "{%0,%1,%2,%3}, {%4,%5,%6,%7}, {%8,%9}, {%0,%1,%2,%3};\n"
        : "+f"(c0), "+f"(c1), "+f"(c2), "+f"(c3)
        : "r"(a0), "r"(a1), "r"(a2), "r"(a3), "r"(b0), "r"(b1));
}

__global__ __launch_bounds__(256, 1) void gemm_kernel(float* __restrict__ out) {
    extern __shared__ char smem_raw[];
    char* sm = (char*)(((uintptr_t)smem_raw + 1023) & ~(uintptr_t)1023);
    uint32_t sbase = s2u(sm);

    int tid = threadIdx.x, lane = tid & 31, wid = tid >> 5;
    int warpm = wid & 1, warpn = wid >> 1;        // 2 x 4 warp grid, warp tile 64x64
    int gid = lane >> 2, tig = lane & 3;

    // base ldmatrix offsets (ks=0); ks variant = base ^ (ks<<5)
    uint32_t aoffb[4], boffb[4];
    {
        int g8 = lane >> 3, rin = lane & 7;
#pragma unroll
        for (int mt = 0; mt < 4; mt++)
            aoffb[mt] = swz(warpm * 64 + mt * 16 + (g8 & 1) * 8 + rin, g8 >> 1);
#pragma unroll
        for (int p = 0; p < 4; p++)
            boffb[p] = A_TILE + swz(warpn * 64 + p * 16 + (g8 >> 1) * 8 + rin, g8 & 1);
    }

    // cp.async bases; slice i adds i*4096 (smem) / i*ROWSTEP (gmem)
    uint32_t sa0 = swz(tid >> 3, tid & 7);
    uint32_t g0  = (uint32_t)((tid >> 3) * KB2 + (tid & 7) * 16);

#define TILE_PTRS(t, A, B)                                                             \
    {                                                                                  \
        A = (const char*)g_a16 + (size_t)((t) / TPN) * BM * KB2;                       \
        B = (const char*)g_b16 + (size_t)((t) % TPN) * BN * KB2;                       \
    }

#define ISSUE_P(Aptr, Bptr, kc)                                                                \
    {                                                                                          \
        uint32_t st = sbase + ((kc) & 3) * STAGE_B + sa0;                                      \
        uint32_t kb = g0 + (kc) * 128;                                                         \
        _Pragma("unroll") for (int i = 0; i < 4; i++)                                          \
            asm volatile("cp.async.cg.shared.global [%0], [%1], 16;"                           \
                         :: "r"(st + i * 4096), "l"((Aptr) + kb + i * ROWSTEP) : "memory");    \
        _Pragma("unroll") for (int i = 0; i < 8; i++)                                          \
            asm volatile("cp.async.cg.shared.global [%0], [%1], 16;"                           \
                         :: "r"(st + A_TILE + i * 4096), "l"((Bptr) + kb + i * ROWSTEP) : "memory"); \
        asm volatile("cp.async.commit_group;" ::: "memory");                                   \
    }

#define LOADFRAG(buf, sA, ks)                                                        \
    {                                                                                \
        _Pragma("unroll") for (int mt = 0; mt < 4; mt++)                             \
            ldsm4(a[buf][mt][0], a[buf][mt][1], a[buf][mt][2], a[buf][mt][3],        \
                  (sA) + (aoffb[mt] ^ ((ks) << 5)));                                 \
        _Pragma("unroll") for (int p = 0; p < 4; p++)                                \
            ldsm4(b[buf][p][0], b[buf][p][1], b[buf][p][2], b[buf][p][3],            \
                  (sA) + (boffb[p] ^ ((ks) << 5)));                                  \
    }

#define MMA_ALL(buf)                                                                         \
    {                                                                                        \
        _Pragma("unroll") for (int mt = 0; mt < 4; mt++)                                     \
            _Pragma("unroll") for (int nt = 0; nt < 8; nt++)                                 \
                mma_f16(c[mt][nt][0], c[mt][nt][1], c[mt][nt][2], c[mt][nt][3],              \
                        a[buf][mt][0], a[buf][mt][1], a[buf][mt][2], a[buf][mt][3],          \
                        b[buf][nt >> 1][(nt & 1) * 2], b[buf][nt >> 1][(nt & 1) * 2 + 1]);   \
    }

    float c[4][8][4];
    uint32_t a[2][4][4], b[2][4][4];

    int t = blockIdx.x;
    if (t >= NTILES) return;
    int tn = t + gridDim.x;                       // next tile for this CTA
    const char *Ag, *Bg, *nAg, *nBg;
    TILE_PTRS(t, Ag, Bg);
    if (tn < NTILES) TILE_PTRS(tn, nAg, nBg) else { nAg = Ag; nBg = Bg; }

#pragma unroll
    for (int mt = 0; mt < 4; mt++)
#pragma unroll
        for (int nt = 0; nt < 8; nt++)
#pragma unroll
            for (int r = 0; r < 4; r++) c[mt][nt][r] = 0.0f;

    // prologue: fill 3 stages of first tile; wait; load ks0 fragments
    ISSUE_P(Ag, Bg, 0); ISSUE_P(Ag, Bg, 1); ISSUE_P(Ag, Bg, 2);
    asm volatile("cp.async.wait_group 2;" ::: "memory");
    __syncthreads();
    LOADFRAG(0, sbase, 0);

    while (true) {
        bool has_next = (tn < NTILES);
        for (int kc = 0; kc < KITERS; ++kc) {
            uint32_t sA = sbase + (kc & 3) * STAGE_B;
            LOADFRAG(1, sA, 1);
            MMA_ALL(0);
            LOADFRAG(0, sA, 2);
            MMA_ALL(1);
            LOADFRAG(1, sA, 3);
            MMA_ALL(0);
            if (kc < KITERS - 1 || has_next) {
                // boundary hidden in the shadow of ks3's MMAs; one group committed
                // per kc ALWAYS (empty commit during drain keeps counting exact)
                asm volatile("cp.async.wait_group 1;" ::: "memory");
                __syncthreads();
                int nk = kc + 3;
                if (nk < KITERS) {
                    ISSUE_P(Ag, Bg, nk);
                } else if (has_next) {
                    ISSUE_P(nAg, nBg, nk - KITERS);
                } else {
                    asm volatile("cp.async.commit_group;" ::: "memory");
                }
                LOADFRAG(0, sbase + (((kc + 1) & 3) * STAGE_B), 0);
                MMA_ALL(1);
            } else {
                MMA_ALL(1);   // very last kc of very last tile: just finish
            }
        }

        // epilogue for tile t (next tile's stages are streaming in meanwhile)
        {
            int bm = t / TPN, bn = t % TPN;
#pragma unroll
            for (int mt = 0; mt < 4; ++mt) {
                int rlo = bm * BM + warpm * 64 + mt * 16 + gid;
                int rhi = rlo + 8;
                float sxl = g_sx[rlo];
                float sxh = g_sx[rhi];
#pragma unroll
                for (int nt = 0; nt < 8; ++nt) {
                    int o0 = bn * BN + warpn * 64 + nt * 8 + tig * 2;
                    float2 vlo = make_float2(sxl * c[mt][nt][0], sxl * c[mt][nt][1]);
                    float2 vhi = make_float2(sxh * c[mt][nt][2], sxh * c[mt][nt][3]);
                    *reinterpret_cast<float2*>(out + (size_t)rlo * N_OUT + o0) = vlo;
                    *reinterpret_cast<float2*>(out + (size_t)rhi * N_OUT + o0) = vhi;
                }
            }
        }
        if (!has_next) break;

        // advance to next tile; its ks0 fragments are already in buffer 0
        t = tn;
        Ag = nAg; Bg = nBg;
        tn = t + gridDim.x;
        if (tn < NTILES) TILE_PTRS(tn, nAg, nBg);
#pragma unroll
        for (int mt = 0; mt < 4; mt++)
#pragma unroll
            for (int nt = 0; nt < 8; nt++)
#pragma unroll
                for (int r = 0; r < 4; r++) c[mt][nt][r] = 0.0f;
    }
}

// ============================================================================
// launch
// ============================================================================
extern "C" void kernel_launch(void* const* d_in, const int* in_sizes, int n_in,
                              void* d_out, int out_size) {
    const float* x      = (const float*)d_in[0];
    const int*   w      = (const int*)d_in[1];     // int8 upcast to int32 by harness
    const float* scales = (const float*)d_in[2];
    const float* zeros  = (const float*)d_in[3];
    float* out = (float*)d_out;

    static int nsm = 0;
    if (nsm == 0) {
        cudaDeviceGetAttribute(&nsm, cudaDevAttrMultiProcessorCount, 0);
        if (nsm <= 0 || nsm > NTILES) nsm = 148;
        cudaFuncSetAttribute(gemm_kernel, cudaFuncAttributeMaxDynamicSharedMemorySize, SMEM_DYN);
    }

    prep_kernel<<<M_TOK + N_OUT, 256>>>(x, w, scales, zeros);
    gemm_kernel<<<nsm, 256, SMEM_DYN>>>(out);
}

// round 13
// speedup vs baseline: 1.1437x; 1.1173x over previous
#include <cuda_runtime.h>
#include <cuda_fp16.h>
#include <cstdint>

#define M_TOK 8192
#define K_DIM 4096
#define N_OUT 4096
#define NGRP  16
#define KB2   (K_DIM * 2)               // row stride in bytes (fp16)

// ---- scratch (device globals; no allocation allowed) ----
__device__ __align__(16) __half g_a16[(size_t)M_TOK * K_DIM];   // fp16(q - zp), exact ints
__device__ __align__(16) __half g_b16[(size_t)N_OUT * K_DIM];   // fp16((w - z) * s)
__device__ float g_sx[M_TOK];                                    // per-token scale

// ============================================================================
// Fused prep kernel: blocks [0,8192) per-token quant -> g_a16,
//                    blocks [8192,12288) weight dequant -> g_b16
// ============================================================================
__global__ __launch_bounds__(256) void prep_kernel(const float* __restrict__ x,
                                                   const int* __restrict__ W,
                                                   const float* __restrict__ scales,
                                                   const float* __restrict__ zeros) {
    int tid = threadIdx.x;
    if (blockIdx.x < M_TOK) {
        int row = blockIdx.x;
        const float4* xr4 = reinterpret_cast<const float4*>(x + (size_t)row * K_DIM) + tid * 4;

        float4 v[4];
#pragma unroll
        for (int i = 0; i < 4; i++) v[i] = xr4[i];

        float mn = 0.0f, mx = 0.0f;
#pragma unroll
        for (int i = 0; i < 4; i++) {
            mn = fminf(mn, fminf(fminf(v[i].x, v[i].y), fminf(v[i].z, v[i].w)));
            mx = fmaxf(mx, fmaxf(fmaxf(v[i].x, v[i].y), fmaxf(v[i].z, v[i].w)));
        }
#pragma unroll
        for (int off = 16; off; off >>= 1) {
            mn = fminf(mn, __shfl_xor_sync(0xffffffffu, mn, off));
            mx = fmaxf(mx, __shfl_xor_sync(0xffffffffu, mx, off));
        }
        __shared__ float smn[8], smx[8];
        if ((tid & 31) == 0) { smn[tid >> 5] = mn; smx[tid >> 5] = mx; }
        __syncthreads();
        mn = smn[0]; mx = smx[0];
#pragma unroll
        for (int i = 1; i < 8; i++) { mn = fminf(mn, smn[i]); mx = fmaxf(mx, smx[i]); }

        float scale = fmaxf((mx - mn) / 255.0f, 1.1920928955078125e-07f);
        float a = mn / scale, b = mx / scale;
        float t = (-128.0f + a) + (127.0f + b);
        float zp0 = (t > 0.0f) ? (-128.0f - a) : (127.0f - b);
        float zpf = fminf(fmaxf(rintf(zp0), -128.0f), 127.0f);
        float rs = 1.0f / scale;    // one IEEE division; per-element FMUL below

        const float* pv = reinterpret_cast<const float*>(v);
        uint32_t packed[8];
#pragma unroll
        for (int j = 0; j < 8; j++) {
            float q0 = fminf(fmaxf(rintf(pv[2 * j] * rs) + zpf, -128.0f), 127.0f);
            float q1 = fminf(fmaxf(rintf(pv[2 * j + 1] * rs) + zpf, -128.0f), 127.0f);
            __half2 h = __floats2half2_rn(q0 - zpf, q1 - zpf);   // exact ints in [-255,255]
            packed[j] = *reinterpret_cast<uint32_t*>(&h);
        }
        uint4* dst = reinterpret_cast<uint4*>(g_a16 + (size_t)row * K_DIM + tid * 16);
        dst[0] = make_uint4(packed[0], packed[1], packed[2], packed[3]);
        dst[1] = make_uint4(packed[4], packed[5], packed[6], packed[7]);
        if (tid == 0) g_sx[row] = scale;
    } else {
        int o = blockIdx.x - M_TOK;
        int g = tid >> 4;
        float z = zeros[o * NGRP + g];
        float s = scales[o * NGRP + g];

        const int4* Wrow = reinterpret_cast<const int4*>(W + (size_t)o * K_DIM) + tid * 4;
        uint32_t packed[8];
#pragma unroll
        for (int c = 0; c < 4; c++) {
            int4 w4 = Wrow[c];
            __half2 h0 = __floats2half2_rn(((float)w4.x - z) * s, ((float)w4.y - z) * s);
            __half2 h1 = __floats2half2_rn(((float)w4.z - z) * s, ((float)w4.w - z) * s);
            packed[2 * c]     = *reinterpret_cast<uint32_t*>(&h0);
            packed[2 * c + 1] = *reinterpret_cast<uint32_t*>(&h1);
        }
        uint4* dst = reinterpret_cast<uint4*>(g_b16 + (size_t)o * K_DIM + tid * 16);
        dst[0] = make_uint4(packed[0], packed[1], packed[2], packed[3]);
        dst[1] = make_uint4(packed[4], packed[5], packed[6], packed[7]);
    }
}

// ============================================================================
// GEMM: persistent CTAs, 128x256 tiles, 64x64 warp tiles, 4-stage cp.async.
// cp.async slices spread across ks batches; continuous stream across tiles.
// ============================================================================
#define BM 128
#define BN 256
#define NSTAGE 4
#define A_TILE (BM * 128)                 // 16384 bytes
#define B_TILE (BN * 128)                 // 32768 bytes
#define STAGE_B (A_TILE + B_TILE)         // 49152
#define SMEM_DYN (NSTAGE * STAGE_B + 1024)
#define KITERS (K_DIM / 64)               // 64 chunks per tile
#define ROWSTEP (32 * KB2)                // gmem delta per cp.async slice
#define NTILES ((M_TOK / BM) * (N_OUT / BN))   // 1024
#define TPN (N_OUT / BN)                  // 16 tiles along n

__device__ __forceinline__ uint32_t s2u(const void* p) {
    uint32_t a;
    asm("{ .reg .u64 t; cvta.to.shared.u64 t, %1; cvt.u32.u64 %0, t; }" : "=r"(a) : "l"(p));
    return a;
}
__device__ __forceinline__ uint32_t swz(uint32_t r, uint32_t c16) {
    uint32_t off = r * 128 + c16 * 16;
    return off ^ ((off >> 3) & 0x70);
}
__device__ __forceinline__ void ldsm4(uint32_t& d0, uint32_t& d1, uint32_t& d2, uint32_t& d3,
                                      uint32_t addr) {
    asm volatile("ldmatrix.sync.aligned.m8n8.x4.shared.b16 {%0,%1,%2,%3}, [%4];"
                 : "=r"(d0), "=r"(d1), "=r"(d2), "=r"(d3) : "r"(addr));
}
__device__ __forceinline__ void mma_f16(float& c0, float& c1, float& c2, float& c3,
                                        uint32_t a0, uint32_t a1, uint32_t a2, uint32_t a3,
                                        uint32_t b0, uint32_t b1) {
    asm volatile(
        "mma.sync.aligned.m16n8k16.row.col.f32.f16.f16.f32 "
        "{%0,%1,%2,%3}, {%4,%5,%6,%7}, {%8,%9}, {%0,%1,%2,%3};\n"
        : "+f"(c0), "+f"(c1), "+f"(c2), "+f"(c3)
        : "r"(a0), "r"(a1), "r"(a2), "r"(a3), "r"(b0), "r"(b1));
}

__global__ __launch_bounds__(256, 1) void gemm_kernel(float* __restrict__ out) {
    extern __shared__ char smem_raw[];
    char* sm = (char*)(((uintptr_t)smem_raw + 1023) & ~(uintptr_t)1023);
    uint32_t sbase = s2u(sm);

    int tid = threadIdx.x, lane = tid & 31, wid = tid >> 5;
    int warpm = wid & 1, warpn = wid >> 1;        // 2 x 4 warp grid, warp tile 64x64
    int gid = lane >> 2, tig = lane & 3;

    uint32_t aoffb[4], boffb[4];
    {
        int g8 = lane >> 3, rin = lane & 7;
#pragma unroll
        for (int mt = 0; mt < 4; mt++)
            aoffb[mt] = swz(warpm * 64 + mt * 16 + (g8 & 1) * 8 + rin, g8 >> 1);
#pragma unroll
        for (int p = 0; p < 4; p++)
            boffb[p] = A_TILE + swz(warpn * 64 + p * 16 + (g8 >> 1) * 8 + rin, g8 & 1);
    }

    uint32_t sa0 = swz(tid >> 3, tid & 7);
    uint32_t g0  = (uint32_t)((tid >> 3) * KB2 + (tid & 7) * 16);

#define TILE_PTRS(t, A, B)                                                             \
    {                                                                                  \
        A = (const char*)g_a16 + (size_t)((t) / TPN) * BM * KB2;                       \
        B = (const char*)g_b16 + (size_t)((t) % TPN) * BN * KB2;                       \
    }

// full-stage issue (prologue only) with commit
#define ISSUE_P(Aptr, Bptr, kc)                                                                \
    {                                                                                          \
        uint32_t st = sbase + ((kc) & 3) * STAGE_B + sa0;                                      \
        uint32_t kb = g0 + (kc) * 128;                                                         \
        _Pragma("unroll") for (int i = 0; i < 4; i++)                                          \
            asm volatile("cp.async.cg.shared.global [%0], [%1], 16;"                           \
                         :: "r"(st + i * 4096), "l"((Aptr) + kb + i * ROWSTEP) : "memory");    \
        _Pragma("unroll") for (int i = 0; i < 8; i++)                                          \
            asm volatile("cp.async.cg.shared.global [%0], [%1], 16;"                           \
                         :: "r"(st + A_TILE + i * 4096), "l"((Bptr) + kb + i * ROWSTEP) : "memory"); \
        asm volatile("cp.async.commit_group;" ::: "memory");                                   \
    }

// partial slices (no commit): A slices i0..i0+1, B slices j0..j0+3 variants
#define SLICE_A4(pA, pst, pkb)                                                                 \
    if (pf) {                                                                                  \
        _Pragma("unroll") for (int i = 0; i < 4; i++)                                          \
            asm volatile("cp.async.cg.shared.global [%0], [%1], 16;"                           \
                         :: "r"((pst) + i * 4096), "l"((pA) + (pkb) + i * ROWSTEP) : "memory"); \
    }
#define SLICE_B4(pB, pst, pkb, j0)                                                             \
    if (pf) {                                                                                  \
        _Pragma("unroll") for (int i = 0; i < 4; i++)                                          \
            asm volatile("cp.async.cg.shared.global [%0], [%1], 16;"                           \
                         :: "r"((pst) + A_TILE + ((j0) + i) * 4096),                           \
                            "l"((pB) + (pkb) + ((j0) + i) * ROWSTEP) : "memory");              \
    }

#define LOADFRAG(buf, sA, ks)                                                        \
    {                                                                                \
        _Pragma("unroll") for (int mt = 0; mt < 4; mt++)                             \
            ldsm4(a[buf][mt][0], a[buf][mt][1], a[buf][mt][2], a[buf][mt][3],        \
                  (sA) + (aoffb[mt] ^ ((ks) << 5)));                                 \
        _Pragma("unroll") for (int p = 0; p < 4; p++)                                \
            ldsm4(b[buf][p][0], b[buf][p][1], b[buf][p][2], b[buf][p][3],            \
                  (sA) + (boffb[p] ^ ((ks) << 5)));                                  \
    }

#define MMA_ALL(buf)                                                                         \
    {                                                                                        \
        _Pragma("unroll") for (int mt = 0; mt < 4; mt++)                                     \
            _Pragma("unroll") for (int nt = 0; nt < 8; nt++)                                 \
                mma_f16(c[mt][nt][0], c[mt][nt][1], c[mt][nt][2], c[mt][nt][3],              \
                        a[buf][mt][0], a[buf][mt][1], a[buf][mt][2], a[buf][mt][3],          \
                        b[buf][nt >> 1][(nt & 1) * 2], b[buf][nt >> 1][(nt & 1) * 2 + 1]);   \
    }

    float c[4][8][4];
    uint32_t a[2][4][4], b[2][4][4];

    int t = blockIdx.x;
    if (t >= NTILES) return;
    int tn = t + gridDim.x;
    const char *Ag, *Bg, *nAg, *nBg;
    TILE_PTRS(t, Ag, Bg);
    if (tn < NTILES) TILE_PTRS(tn, nAg, nBg) else { nAg = Ag; nBg = Bg; }

#pragma unroll
    for (int mt = 0; mt < 4; mt++)
#pragma unroll
        for (int nt = 0; nt < 8; nt++)
#pragma unroll
            for (int r = 0; r < 4; r++) c[mt][nt][r] = 0.0f;

    // prologue
    ISSUE_P(Ag, Bg, 0); ISSUE_P(Ag, Bg, 1); ISSUE_P(Ag, Bg, 2);
    asm volatile("cp.async.wait_group 2;" ::: "memory");
    __syncthreads();
    LOADFRAG(0, sbase, 0);

    while (true) {
        bool has_next = (tn < NTILES);
        for (int kc = 0; kc < KITERS; ++kc) {
            uint32_t sA = sbase + (kc & 3) * STAGE_B;
            // prefetch target: stage kc+3 (may belong to next tile)
            int nk = kc + 3;
            bool pf;
            const char *pA, *pB;
            uint32_t pst, pkb;
            if (nk < KITERS) {
                pf = true; pA = Ag; pB = Bg;
                pkb = g0 + nk * 128;
            } else if (has_next) {
                pf = true; pA = nAg; pB = nBg;
                pkb = g0 + (nk - KITERS) * 128;
            } else {
                pf = false; pA = Ag; pB = Bg; pkb = g0;
            }
            pst = sbase + (nk & 3) * STAGE_B + sa0;

            LOADFRAG(1, sA, 1);
            SLICE_A4(pA, pst, pkb);
            MMA_ALL(0);
            LOADFRAG(0, sA, 2);
            SLICE_B4(pB, pst, pkb, 0);
            MMA_ALL(1);
            LOADFRAG(1, sA, 3);
            SLICE_B4(pB, pst, pkb, 4);
            MMA_ALL(0);
            if (kc < KITERS - 1 || has_next) {
                // boundary in the shadow of ks3's MMAs; exactly one commit per kc
                asm volatile("cp.async.wait_group 1;" ::: "memory");
                __syncthreads();
                asm volatile("cp.async.commit_group;" ::: "memory");
                LOADFRAG(0, sbase + (((kc + 1) & 3) * STAGE_B), 0);
                MMA_ALL(1);
            } else {
                MMA_ALL(1);
            }
        }

        // epilogue for tile t (next tile's stages stream in meanwhile)
        {
            int bm = t / TPN, bn = t % TPN;
#pragma unroll
            for (int mt = 0; mt < 4; ++mt) {
                int rlo = bm * BM + warpm * 64 + mt * 16 + gid;
                int rhi = rlo + 8;
                float sxl = g_sx[rlo];
                float sxh = g_sx[rhi];
#pragma unroll
                for (int nt = 0; nt < 8; ++nt) {
                    int o0 = bn * BN + warpn * 64 + nt * 8 + tig * 2;
                    float2 vlo = make_float2(sxl * c[mt][nt][0], sxl * c[mt][nt][1]);
                    float2 vhi = make_float2(sxh * c[mt][nt][2], sxh * c[mt][nt][3]);
                    *reinterpret_cast<float2*>(out + (size_t)rlo * N_OUT + o0) = vlo;
                    *reinterpret_cast<float2*>(out + (size_t)rhi * N_OUT + o0) = vhi;
                }
            }
        }
        if (!has_next) break;

        t = tn;
        Ag = nAg; Bg = nBg;
        tn = t + gridDim.x;
        if (tn < NTILES) TILE_PTRS(tn, nAg, nBg);
#pragma unroll
        for (int mt = 0; mt < 4; mt++)
#pragma unroll
            for (int nt = 0; nt < 8; nt++)
#pragma unroll
                for (int r = 0; r < 4; r++) c[mt][nt][r] = 0.0f;
    }
}

// ============================================================================
// launch
// ============================================================================
extern "C" void kernel_launch(void* const* d_in, const int* in_sizes, int n_in,
                              void* d_out, int out_size) {
    const float* x      = (const float*)d_in[0];
    const int*   w      = (const int*)d_in[1];     // int8 upcast to int32 by harness
    const float* scales = (const float*)d_in[2];
    const float* zeros  = (const float*)d_in[3];
    float* out = (float*)d_out;

    static int nsm = 0;
    if (nsm == 0) {
        cudaDeviceGetAttribute(&nsm, cudaDevAttrMultiProcessorCount, 0);
        if (nsm <= 0 || nsm > NTILES) nsm = 148;
        cudaFuncSetAttribute(gemm_kernel, cudaFuncAttributeMaxDynamicSharedMemorySize, SMEM_DYN);
    }

    prep_kernel<<<M_TOK + N_OUT, 256>>>(x, w, scales, zeros);
    gemm_kernel<<<nsm, 256, SMEM_DYN>>>(out);
}